// round 15
// baseline (speedup 1.0000x reference)
#include <cuda_runtime.h>
#include <cuda_fp16.h>
#include <stdint.h>

// Problem constants
#define Bq   4
#define Tq   2048
#define Dq   1024
#define Hq   16
#define HDq  64
#define Mq   (Bq * Tq)        // 8192
#define DFF  (4 * Dq)         // 4096
#define LN_EPS 1e-5f
#define ATT_SCALE 0.125f

// ---------------------------------------------------------------------------
// Scratch
// ---------------------------------------------------------------------------
__device__ __half g_h[Mq * Dq];            // LN out fp16
__device__ __half g_wqkv[3*Dq*Dq];         // [3D][D] fp16
__device__ __half g_wp[Dq*Dq];             // [D][D] transposed fp16
__device__ __half g_w1[DFF*Dq];            // [4D][D] fp16
__device__ __half g_w2[Dq*DFF];            // [D][4D] fp16
__device__ __half g_qkv[Mq * 3 * Dq];      // q pre-scaled, fp16
__device__ __half g_attn[Mq * Dq];         // flash out fp16
__device__ float  g_x1[Mq * Dq];
__device__ __half g_ff[Mq * DFF];          // FFN hidden fp16

// ---------------------------------------------------------------------------
// Helpers
// ---------------------------------------------------------------------------
__device__ __forceinline__ uint32_t packh2(float x, float y) {
    __half2 h = __floats2half2_rn(x, y);
    return *reinterpret_cast<uint32_t*>(&h);
}

__device__ __forceinline__ void mma_f16(float* c, const uint32_t* a, const uint32_t* b) {
    asm volatile(
        "mma.sync.aligned.m16n8k16.row.col.f32.f16.f16.f32 "
        "{%0,%1,%2,%3}, {%4,%5,%6,%7}, {%8,%9}, {%0,%1,%2,%3};"
        : "+f"(c[0]), "+f"(c[1]), "+f"(c[2]), "+f"(c[3])
        : "r"(a[0]), "r"(a[1]), "r"(a[2]), "r"(a[3]), "r"(b[0]), "r"(b[1]));
}

__device__ __forceinline__ void ldmx4(uint32_t* r, const void* p) {
    uint32_t a = (uint32_t)__cvta_generic_to_shared(p);
    asm volatile("ldmatrix.sync.aligned.m8n8.x4.shared.b16 {%0,%1,%2,%3}, [%4];"
                 : "=r"(r[0]), "=r"(r[1]), "=r"(r[2]), "=r"(r[3]) : "r"(a));
}

__device__ __forceinline__ void ldmx2t(uint32_t& r0, uint32_t& r1, const void* p) {
    uint32_t a = (uint32_t)__cvta_generic_to_shared(p);
    asm volatile("ldmatrix.sync.aligned.m8n8.x2.trans.shared.b16 {%0,%1}, [%2];"
                 : "=r"(r0), "=r"(r1) : "r"(a));
}

__device__ __forceinline__ void cp16(void* sdst, const void* gsrc) {
    unsigned sa = (unsigned)__cvta_generic_to_shared(sdst);
    asm volatile("cp.async.cg.shared.global [%0], [%1], 16;" :: "r"(sa), "l"(gsrc));
}
#define CP_COMMIT() asm volatile("cp.async.commit_group;")
#define CP_WAIT0()  asm volatile("cp.async.wait_group 0;")
#define CP_WAIT1()  asm volatile("cp.async.wait_group 1;")

// ---------------------------------------------------------------------------
// Merged prep + LN1: blocks [0,12288) transpose weights; [12288,20480) do LN1.
// 256 threads/block.
// ---------------------------------------------------------------------------
__global__ void prep_ln(const float* __restrict__ Wq,
                        const float* __restrict__ Wk,
                        const float* __restrict__ Wv,
                        const float* __restrict__ Wp,
                        const float* __restrict__ W1,
                        const float* __restrict__ W2,
                        const float* __restrict__ x,
                        const float* __restrict__ g1,
                        const float* __restrict__ be1,
                        __half* __restrict__ o_qkv,
                        __half* __restrict__ o_p,
                        __half* __restrict__ o_1,
                        __half* __restrict__ o_2,
                        __half* __restrict__ o_h)
{
    __shared__ float t[32][33];
    int bid = blockIdx.x;
    int tid = threadIdx.x;

    if (bid >= 12288) {
        // ---- LayerNorm row ----
        float* red = &t[0][0];
        int row = bid - 12288;
        const float4* xr = (const float4*)(x + (long)row * Dq);
        float4 v = xr[tid];
        float s  = v.x + v.y + v.z + v.w;
        float ss = v.x * v.x + v.y * v.y + v.z * v.z + v.w * v.w;
        #pragma unroll
        for (int o2 = 16; o2 >= 1; o2 >>= 1) {
            s  += __shfl_xor_sync(0xffffffffu, s,  o2);
            ss += __shfl_xor_sync(0xffffffffu, ss, o2);
        }
        if ((tid & 31) == 0) { red[tid >> 5] = s; red[8 + (tid >> 5)] = ss; }
        __syncthreads();
        float stot = 0.f, sstot = 0.f;
        #pragma unroll
        for (int w = 0; w < 8; w++) { stot += red[w]; sstot += red[8 + w]; }
        float mu  = stot * (1.f / Dq);
        float var = sstot * (1.f / Dq) - mu * mu;
        float inv = rsqrtf(var + LN_EPS);
        float4 gg = ((const float4*)g1)[tid];
        float4 bb = ((const float4*)be1)[tid];
        __half2 p0 = __floats2half2_rn((v.x - mu) * inv * gg.x + bb.x,
                                       (v.y - mu) * inv * gg.y + bb.y);
        __half2 p1 = __floats2half2_rn((v.z - mu) * inv * gg.z + bb.z,
                                       (v.w - mu) * inv * gg.w + bb.w);
        long base = (long)row * Dq + tid * 4;
        *(__half2*)(o_h + base)     = p0;
        *(__half2*)(o_h + base + 2) = p1;
        return;
    }

    int tx = tid & 31, ty = tid >> 5;
    if (bid < 3072) {
        int sh = bid >> 6;
        int tI = bid & 63;
        int s = sh >> 4, h = sh & 15;
        const float* W = (s == 0) ? Wq : (s == 1) ? Wk : Wv;
        const float* in = W + (long)h * Dq * HDq;
        int d0  = (tI >> 1) * 32;
        int hd0 = (tI & 1) * 32;
        #pragma unroll
        for (int i = 0; i < 32; i += 8)
            t[ty + i][tx] = in[(long)(d0 + ty + i) * HDq + hd0 + tx];
        __syncthreads();
        long nrow = (long)s * Dq + h * HDq + hd0;
        #pragma unroll
        for (int i = 0; i < 32; i += 8)
            o_qkv[(nrow + ty + i) * Dq + d0 + tx] = __float2half(t[tx][ty + i]);
        return;
    }

    const float* in; __half* out; int K, N;
    bid -= 3072;
    if (bid < 1024)      { in = Wp; out = o_p; K = Dq;  N = Dq;  }
    else if (bid < 5120) { bid -= 1024; in = W1; out = o_1; K = Dq;  N = DFF; }
    else                 { bid -= 5120; in = W2; out = o_2; K = DFF; N = Dq;  }

    int ntn = N >> 5;
    int k0 = (bid / ntn) * 32;
    int n0 = (bid % ntn) * 32;
    #pragma unroll
    for (int i = 0; i < 32; i += 8)
        t[ty + i][tx] = in[(long)(k0 + ty + i) * N + n0 + tx];
    __syncthreads();
    #pragma unroll
    for (int i = 0; i < 32; i += 8)
        out[(long)(n0 + ty + i) * K + k0 + tx] = __float2half(t[tx][ty + i]);
}

// ---------------------------------------------------------------------------
// Standalone LN (for LN2)
// ---------------------------------------------------------------------------
__global__ void ln_f16(const float* __restrict__ x,
                       const float* __restrict__ g,
                       const float* __restrict__ b,
                       __half* __restrict__ o)
{
    __shared__ float red[16];
    int row = blockIdx.x;
    int t = threadIdx.x;
    const float4* xr = (const float4*)(x + (long)row * Dq);
    float4 v = xr[t];
    float s  = v.x + v.y + v.z + v.w;
    float ss = v.x * v.x + v.y * v.y + v.z * v.z + v.w * v.w;
    #pragma unroll
    for (int o2 = 16; o2 >= 1; o2 >>= 1) {
        s  += __shfl_xor_sync(0xffffffffu, s,  o2);
        ss += __shfl_xor_sync(0xffffffffu, ss, o2);
    }
    if ((t & 31) == 0) { red[t >> 5] = s; red[8 + (t >> 5)] = ss; }
    __syncthreads();
    float stot = 0.f, sstot = 0.f;
    #pragma unroll
    for (int w = 0; w < 8; w++) { stot += red[w]; sstot += red[8 + w]; }
    float mu  = stot * (1.f / Dq);
    float var = sstot * (1.f / Dq) - mu * mu;
    float inv = rsqrtf(var + LN_EPS);
    float4 gg = ((const float4*)g)[t];
    float4 bb = ((const float4*)b)[t];
    __half2 p0 = __floats2half2_rn((v.x - mu) * inv * gg.x + bb.x,
                                   (v.y - mu) * inv * gg.y + bb.y);
    __half2 p1 = __floats2half2_rn((v.z - mu) * inv * gg.z + bb.z,
                                   (v.w - mu) * inv * gg.w + bb.w);
    long base = (long)row * Dq + t * 4;
    *(__half2*)(o + base)     = p0;
    *(__half2*)(o + base + 2) = p1;
}

// ---------------------------------------------------------------------------
// Plain fp16 GEMM: C = A @ B.  Tile 128x128, BK=64, 8 warps (2x4),
// warp tile 64x32, 3-stage cp.async (prefetch distance 2), 2 CTAs/SM.
// EPI: 2 +bias+residual fp32; 3 +bias+relu -> fp16; 4 -> fp16 w/ q prescale
// ---------------------------------------------------------------------------
#define KPAD 72
#define AST (128 * KPAD)
#define BST (128 * KPAD)
#define STAGE (AST + BST)           // 18432 halves = 36864 B
#define GEMM_SMEM (3 * STAGE * 2)   // 110592 B

template <int EPI>
__global__ void __launch_bounds__(256, 2)
gemm_f16(const __half* __restrict__ A,
         const __half* __restrict__ B,
         const float* __restrict__ bias,
         const float* __restrict__ res,
         float* __restrict__ C,
         __half* __restrict__ Ch,
         int N, int K)
{
    extern __shared__ __half smem[];
    const int tid  = threadIdx.x;
    const int lane = tid & 31;
    const int warp = tid >> 5;
    const int wm = warp >> 2;
    const int wn = warp & 3;
    const int a_r = lane & 15;
    const int a_c = (lane >> 4) << 3;
    const int b_r = (lane & 7) + ((lane >> 4) << 3);
    const int b_c = ((lane >> 3) & 1) << 3;

    const int bm = blockIdx.y, bn = blockIdx.x;
    const __half* A_b = A + (long)bm * 128 * K;
    const __half* B_b = B + (long)bn * 128 * K;

    auto sA = [&](int st) -> __half* { return smem + st * STAGE; };
    auto sB = [&](int st) -> __half* { return smem + st * STAGE + AST; };

    auto ld_stage = [&](int st, int kt) {
        long k0 = (long)kt * 64;
        #pragma unroll
        for (int i = 0; i < 4; i++) {
            int c = tid + i * 256;
            int row = c >> 3, ch = (c & 7) * 8;
            cp16(sA(st) + row * KPAD + ch, A_b + (long)row * K + k0 + ch);
        }
        #pragma unroll
        for (int i = 0; i < 4; i++) {
            int c = tid + i * 256;
            int row = c >> 3, ch = (c & 7) * 8;
            cp16(sB(st) + row * KPAD + ch, B_b + (long)row * K + k0 + ch);
        }
    };

    float acc[4][4][4];
    #pragma unroll
    for (int i = 0; i < 4; i++)
        #pragma unroll
        for (int j = 0; j < 4; j++)
            #pragma unroll
            for (int r = 0; r < 4; r++) acc[i][j][r] = 0.f;

    const int KT = K / 64;
    ld_stage(0, 0); CP_COMMIT();
    ld_stage(1, 1); CP_COMMIT();

    int st = 0;
    for (int kt = 0; kt < KT; kt++) {
        if (kt + 1 < KT) { CP_WAIT1(); } else { CP_WAIT0(); }
        __syncthreads();
        if (kt + 2 < KT) {
            int wst = st + 2; if (wst >= 3) wst -= 3;
            ld_stage(wst, kt + 2);
            CP_COMMIT();
        }
        const __half* pA = sA(st);
        const __half* pB = sB(st);

        #pragma unroll
        for (int ks = 0; ks < 4; ks++) {
            const int k16 = ks * 16;
            uint32_t af[4][4], bf[4][2];
            #pragma unroll
            for (int mt = 0; mt < 4; mt++)
                ldmx4(af[mt], pA + (wm * 64 + mt * 16 + a_r) * KPAD + k16 + a_c);
            #pragma unroll
            for (int np = 0; np < 2; np++) {
                int row = wn * 32 + np * 16 + b_r;
                uint32_t r[4];
                ldmx4(r, pB + row * KPAD + k16 + b_c);
                bf[2*np][0] = r[0]; bf[2*np][1] = r[1];
                bf[2*np+1][0] = r[2]; bf[2*np+1][1] = r[3];
            }
            #pragma unroll
            for (int mt = 0; mt < 4; mt++)
                #pragma unroll
                for (int nt = 0; nt < 4; nt++)
                    mma_f16(acc[mt][nt], af[mt], bf[nt]);
        }
        if (++st == 3) st = 0;
    }

    // epilogue
    const int lr4 = lane >> 2;
    const int lc2 = (lane & 3) * 2;
    #pragma unroll
    for (int mt = 0; mt < 4; mt++) {
        #pragma unroll
        for (int nt = 0; nt < 4; nt++) {
            int c = bn * 128 + wn * 32 + nt * 8 + lc2;
            #pragma unroll
            for (int half = 0; half < 2; half++) {
                int r = bm * 128 + wm * 64 + mt * 16 + lr4 + half * 8;
                float v0 = acc[mt][nt][half * 2 + 0];
                float v1 = acc[mt][nt][half * 2 + 1];
                long off = (long)r * N + c;
                if (EPI == 2) {
                    float2 bv = *(const float2*)(bias + c);
                    float2 rv = *(const float2*)(res + off);
                    *(float2*)(C + off) = make_float2(v0 + bv.x + rv.x,
                                                      v1 + bv.y + rv.y);
                } else if (EPI == 3) {
                    float2 bv = *(const float2*)(bias + c);
                    v0 = fmaxf(v0 + bv.x, 0.f);
                    v1 = fmaxf(v1 + bv.y, 0.f);
                    *(__half2*)(Ch + off) = __floats2half2_rn(v0, v1);
                } else {  // EPI == 4: fp16, q cols prescaled
                    float scale = (c < Dq) ? ATT_SCALE : 1.f;
                    *(__half2*)(Ch + off) = __floats2half2_rn(v0 * scale, v1 * scale);
                }
            }
        }
    }
}

// ---------------------------------------------------------------------------
// Flash attention, plain fp16, KV tile 64, double buffered, 2 CTAs/SM.
// ---------------------------------------------------------------------------
#define FPAD 72
#define FLASH_SMEM ((128 * FPAD + 2 * 2 * 64 * FPAD) * 2)   // 55296 B

__global__ void __launch_bounds__(256, 2)
flash_tc(const __half* __restrict__ qkv,
         __half* __restrict__ outp)
{
    extern __shared__ __half sm[];
    __half* QH = sm;

    const int qi  = gridDim.x - 1 - blockIdx.x;
    const int bh  = blockIdx.y;
    const int b   = bh >> 4;
    const int h   = bh & 15;
    const int tid  = threadIdx.x;
    const int lane = tid & 31;
    const int warp = tid >> 5;
    const int g  = lane >> 2;
    const int t2 = (lane & 3) * 2;
    const int a_r = lane & 15;
    const int a_c = (lane >> 4) << 3;
    const int b_r = (lane & 7) + ((lane >> 4) << 3);
    const int b_c = ((lane >> 3) & 1) << 3;

    const long rb = (long)b * Tq;
    const __half* qp = qkv + (rb + qi * 128) * (3 * Dq) + h * HDq;
    const __half* kp = qkv + rb * (3 * Dq) + Dq + h * HDq;
    const __half* vp = qkv + rb * (3 * Dq) + 2 * Dq + h * HDq;

    auto kvbase = [&](int st) -> __half* {
        return sm + 128 * FPAD + st * (2 * 64 * FPAD);
    };
    auto ldkv = [&](int st, int jt) {
        __half* KB = kvbase(st);
        #pragma unroll
        for (int i = 0; i < 2; i++) {
            int c = tid + i * 256;
            int row = c >> 3;
            int c8 = (c & 7) * 8;
            long go = (long)(jt * 64 + row) * (3 * Dq) + c8;
            int so = row * FPAD + c8;
            cp16(KB + so,             kp + go);
            cp16(KB + 64 * FPAD + so, vp + go);
        }
    };

    #pragma unroll
    for (int i = 0; i < 4; i++) {
        int c = tid + i * 256;
        int row = c >> 3;
        int c8 = (c & 7) * 8;
        cp16(QH + row * FPAD + c8, qp + (long)row * (3 * Dq) + c8);
    }
    ldkv(0, 0);
    CP_COMMIT();

    float oacc[8][4];
    #pragma unroll
    for (int nt = 0; nt < 8; nt++)
        #pragma unroll
        for (int e = 0; e < 4; e++) oacc[nt][e] = 0.f;
    float m0 = -1e30f, m1 = -1e30f, l0 = 0.f, l1 = 0.f;

    uint32_t qf[4][4];
    const int qrow0 = qi * 128 + warp * 16 + g;
    const int jmax = 2 * qi + 1;

    for (int jt = 0; jt <= jmax; jt++) {
        CP_WAIT0();
        __syncthreads();
        if (jt < jmax) { ldkv((jt + 1) & 1, jt + 1); CP_COMMIT(); }

        if (jt == 0) {
            #pragma unroll
            for (int kt = 0; kt < 4; kt++)
                ldmx4(qf[kt], QH + (warp * 16 + a_r) * FPAD + kt * 16 + a_c);
        }

        if (jt * 64 <= qi * 128 + warp * 16 + 15) {
            __half* KB = kvbase(jt & 1);
            const __half* KHs = KB;
            const __half* VHs = KB + 64 * FPAD;

            float sacc[8][4];
            #pragma unroll
            for (int nt = 0; nt < 8; nt++)
                #pragma unroll
                for (int e = 0; e < 4; e++) sacc[nt][e] = 0.f;

            #pragma unroll
            for (int kt = 0; kt < 4; kt++) {
                uint32_t bf[8][2];
                #pragma unroll
                for (int np = 0; np < 4; np++) {
                    int row = np * 16 + b_r;
                    uint32_t r[4];
                    ldmx4(r, KHs + row * FPAD + kt * 16 + b_c);
                    bf[2*np][0] = r[0]; bf[2*np][1] = r[1];
                    bf[2*np+1][0] = r[2]; bf[2*np+1][1] = r[3];
                }
                #pragma unroll
                for (int nt = 0; nt < 8; nt++)
                    mma_f16(sacc[nt], qf[kt], bf[nt]);
            }

            if (jt * 64 + 63 > qrow0) {
                #pragma unroll
                for (int nt = 0; nt < 8; nt++) {
                    int key0 = jt * 64 + nt * 8 + t2;
                    if (key0     > qrow0)     sacc[nt][0] = -1e30f;
                    if (key0 + 1 > qrow0)     sacc[nt][1] = -1e30f;
                    if (key0     > qrow0 + 8) sacc[nt][2] = -1e30f;
                    if (key0 + 1 > qrow0 + 8) sacc[nt][3] = -1e30f;
                }
            }

            float mx0 = -1e30f, mx1 = -1e30f;
            #pragma unroll
            for (int nt = 0; nt < 8; nt++) {
                mx0 = fmaxf(mx0, fmaxf(sacc[nt][0], sacc[nt][1]));
                mx1 = fmaxf(mx1, fmaxf(sacc[nt][2], sacc[nt][3]));
            }
            mx0 = fmaxf(mx0, __shfl_xor_sync(0xffffffffu, mx0, 1));
            mx0 = fmaxf(mx0, __shfl_xor_sync(0xffffffffu, mx0, 2));
            mx1 = fmaxf(mx1, __shfl_xor_sync(0xffffffffu, mx1, 1));
            mx1 = fmaxf(mx1, __shfl_xor_sync(0xffffffffu, mx1, 2));
            float mn0 = fmaxf(m0, mx0), mn1 = fmaxf(m1, mx1);
            float a0 = __expf(m0 - mn0), a1 = __expf(m1 - mn1);
            m0 = mn0; m1 = mn1;
            float rs0 = 0.f, rs1 = 0.f;
            #pragma unroll
            for (int nt = 0; nt < 8; nt++) {
                sacc[nt][0] = __expf(sacc[nt][0] - mn0); rs0 += sacc[nt][0];
                sacc[nt][1] = __expf(sacc[nt][1] - mn0); rs0 += sacc[nt][1];
                sacc[nt][2] = __expf(sacc[nt][2] - mn1); rs1 += sacc[nt][2];
                sacc[nt][3] = __expf(sacc[nt][3] - mn1); rs1 += sacc[nt][3];
            }
            rs0 += __shfl_xor_sync(0xffffffffu, rs0, 1);
            rs0 += __shfl_xor_sync(0xffffffffu, rs0, 2);
            rs1 += __shfl_xor_sync(0xffffffffu, rs1, 1);
            rs1 += __shfl_xor_sync(0xffffffffu, rs1, 2);
            l0 = l0 * a0 + rs0;
            l1 = l1 * a1 + rs1;
            #pragma unroll
            for (int nt = 0; nt < 8; nt++) {
                oacc[nt][0] *= a0; oacc[nt][1] *= a0;
                oacc[nt][2] *= a1; oacc[nt][3] *= a1;
            }

            #pragma unroll
            for (int j = 0; j < 4; j++) {
                uint32_t ph[4];
                ph[0] = packh2(sacc[2*j][0],   sacc[2*j][1]);
                ph[1] = packh2(sacc[2*j][2],   sacc[2*j][3]);
                ph[2] = packh2(sacc[2*j+1][0], sacc[2*j+1][1]);
                ph[3] = packh2(sacc[2*j+1][2], sacc[2*j+1][3]);
                #pragma unroll
                for (int nt = 0; nt < 8; nt++) {
                    uint32_t vf[2];
                    ldmx2t(vf[0], vf[1], VHs + (j * 16 + (lane & 15)) * FPAD + nt * 8);
                    mma_f16(oacc[nt], ph, vf);
                }
            }
        }
    }

    float inv0 = 1.f / l0, inv1 = 1.f / l1;
    long row0 = (long)b * Tq + qi * 128 + warp * 16 + g;
    #pragma unroll
    for (int nt = 0; nt < 8; nt++) {
        int col = h * HDq + nt * 8 + t2;
        *(__half2*)(outp + row0 * Dq + col) =
            __floats2half2_rn(oacc[nt][0] * inv0, oacc[nt][1] * inv0);
        *(__half2*)(outp + (row0 + 8) * Dq + col) =
            __floats2half2_rn(oacc[nt][2] * inv1, oacc[nt][3] * inv1);
    }
}

// ---------------------------------------------------------------------------
// Launch
// ---------------------------------------------------------------------------
extern "C" void kernel_launch(void* const* d_in, const int* in_sizes, int n_in,
                              void* d_out, int out_size)
{
    const float* x   = (const float*)d_in[0];
    const float* Wq  = (const float*)d_in[1];
    const float* Wk  = (const float*)d_in[2];
    const float* Wv  = (const float*)d_in[3];
    const float* Wp  = (const float*)d_in[4];
    const float* bp  = (const float*)d_in[5];
    const float* W1  = (const float*)d_in[6];
    const float* b1  = (const float*)d_in[7];
    const float* W2  = (const float*)d_in[8];
    const float* b2  = (const float*)d_in[9];
    const float* g1  = (const float*)d_in[10];
    const float* be1 = (const float*)d_in[11];
    const float* g2  = (const float*)d_in[12];
    const float* be2 = (const float*)d_in[13];
    float* out = (float*)d_out;

    __half *p_h, *p_wqkv, *p_wp, *p_w1, *p_w2, *p_attn, *p_ff, *p_qkv;
    float *p_x1;
    cudaGetSymbolAddress((void**)&p_h,    g_h);
    cudaGetSymbolAddress((void**)&p_wqkv, g_wqkv);
    cudaGetSymbolAddress((void**)&p_wp,   g_wp);
    cudaGetSymbolAddress((void**)&p_w1,   g_w1);
    cudaGetSymbolAddress((void**)&p_w2,   g_w2);
    cudaGetSymbolAddress((void**)&p_qkv,  g_qkv);
    cudaGetSymbolAddress((void**)&p_attn, g_attn);
    cudaGetSymbolAddress((void**)&p_x1,   g_x1);
    cudaGetSymbolAddress((void**)&p_ff,   g_ff);

    cudaFuncSetAttribute(gemm_f16<2>, cudaFuncAttributeMaxDynamicSharedMemorySize, GEMM_SMEM);
    cudaFuncSetAttribute(gemm_f16<3>, cudaFuncAttributeMaxDynamicSharedMemorySize, GEMM_SMEM);
    cudaFuncSetAttribute(gemm_f16<4>, cudaFuncAttributeMaxDynamicSharedMemorySize, GEMM_SMEM);
    cudaFuncSetAttribute(flash_tc,    cudaFuncAttributeMaxDynamicSharedMemorySize, FLASH_SMEM);

    // merged weight prep + LN1 (single launch)
    prep_ln<<<12288 + Mq, 256>>>(Wq, Wk, Wv, Wp, W1, W2, x, g1, be1,
                                 p_wqkv, p_wp, p_w1, p_w2, p_h);

    // QKV projection -> fp16, q prescaled
    gemm_f16<4><<<dim3(3 * Dq / 128, Mq / 128), 256, GEMM_SMEM>>>(
        p_h, p_wqkv, nullptr, nullptr, nullptr, p_qkv, 3 * Dq, Dq);
    // flash attention -> fp16
    flash_tc<<<dim3(Tq / 128, Bq * Hq), 256, FLASH_SMEM>>>(p_qkv, p_attn);
    // output projection + bias + residual(x)
    gemm_f16<2><<<dim3(Dq / 128, Mq / 128), 256, GEMM_SMEM>>>(
        p_attn, p_wp, bp, x, p_x1, nullptr, Dq, Dq);
    // LN2 -> fp16
    ln_f16<<<Mq, 256>>>(p_x1, g2, be2, p_h);
    // FFN up + bias + relu -> fp16
    gemm_f16<3><<<dim3(DFF / 128, Mq / 128), 256, GEMM_SMEM>>>(
        p_h, p_w1, b1, nullptr, nullptr, p_ff, DFF, Dq);
    // FFN down + bias + residual(x1) -> d_out
    gemm_f16<2><<<dim3(Dq / 128, Mq / 128), 256, GEMM_SMEM>>>(
        p_ff, p_w2, b2, p_x1, out, nullptr, Dq, DFF);
}

// round 16
// speedup vs baseline: 1.5502x; 1.5502x over previous
#include <cuda_runtime.h>
#include <cuda_fp16.h>
#include <stdint.h>

// Problem constants
#define Bq   4
#define Tq   2048
#define Dq   1024
#define Hq   16
#define HDq  64
#define Mq   (Bq * Tq)        // 8192
#define DFF  (4 * Dq)         // 4096
#define LN_EPS 1e-5f
#define ATT_SCALE 0.125f

// ---------------------------------------------------------------------------
// Scratch
// ---------------------------------------------------------------------------
__device__ __half g_h[Mq * Dq];            // LN out fp16
__device__ __half g_wqkv[3*Dq*Dq];         // [3D][D] fp16
__device__ __half g_wp[Dq*Dq];             // [D][D] transposed fp16
__device__ __half g_w1[DFF*Dq];            // [4D][D] fp16
__device__ __half g_w2[Dq*DFF];            // [D][4D] fp16
__device__ __half g_qkv[Mq * 3 * Dq];      // q pre-scaled, fp16
__device__ __half g_attn[Mq * Dq];         // flash out fp16
__device__ float  g_x1[Mq * Dq];
__device__ __half g_ff[Mq * DFF];          // FFN hidden fp16

// ---------------------------------------------------------------------------
// Helpers
// ---------------------------------------------------------------------------
__device__ __forceinline__ uint32_t packh2(float x, float y) {
    __half2 h = __floats2half2_rn(x, y);
    return *reinterpret_cast<uint32_t*>(&h);
}

__device__ __forceinline__ void mma_f16(float* c, const uint32_t* a, const uint32_t* b) {
    asm volatile(
        "mma.sync.aligned.m16n8k16.row.col.f32.f16.f16.f32 "
        "{%0,%1,%2,%3}, {%4,%5,%6,%7}, {%8,%9}, {%0,%1,%2,%3};"
        : "+f"(c[0]), "+f"(c[1]), "+f"(c[2]), "+f"(c[3])
        : "r"(a[0]), "r"(a[1]), "r"(a[2]), "r"(a[3]), "r"(b[0]), "r"(b[1]));
}

__device__ __forceinline__ void ldmx4(uint32_t* r, const void* p) {
    uint32_t a = (uint32_t)__cvta_generic_to_shared(p);
    asm volatile("ldmatrix.sync.aligned.m8n8.x4.shared.b16 {%0,%1,%2,%3}, [%4];"
                 : "=r"(r[0]), "=r"(r[1]), "=r"(r[2]), "=r"(r[3]) : "r"(a));
}

__device__ __forceinline__ void ldmx2t(uint32_t& r0, uint32_t& r1, const void* p) {
    uint32_t a = (uint32_t)__cvta_generic_to_shared(p);
    asm volatile("ldmatrix.sync.aligned.m8n8.x2.trans.shared.b16 {%0,%1}, [%2];"
                 : "=r"(r0), "=r"(r1) : "r"(a));
}

__device__ __forceinline__ void cp16(void* sdst, const void* gsrc) {
    unsigned sa = (unsigned)__cvta_generic_to_shared(sdst);
    asm volatile("cp.async.cg.shared.global [%0], [%1], 16;" :: "r"(sa), "l"(gsrc));
}
#define CP_COMMIT() asm volatile("cp.async.commit_group;")
#define CP_WAIT0()  asm volatile("cp.async.wait_group 0;")

// ---------------------------------------------------------------------------
// Merged prep + LN1: blocks [0,12288) transpose weights; [12288,20480) do LN1.
// ---------------------------------------------------------------------------
__global__ void prep_ln(const float* __restrict__ Wq,
                        const float* __restrict__ Wk,
                        const float* __restrict__ Wv,
                        const float* __restrict__ Wp,
                        const float* __restrict__ W1,
                        const float* __restrict__ W2,
                        const float* __restrict__ x,
                        const float* __restrict__ g1,
                        const float* __restrict__ be1,
                        __half* __restrict__ o_qkv,
                        __half* __restrict__ o_p,
                        __half* __restrict__ o_1,
                        __half* __restrict__ o_2,
                        __half* __restrict__ o_h)
{
    __shared__ float t[32][33];
    int bid = blockIdx.x;
    int tid = threadIdx.x;

    if (bid >= 12288) {
        float* red = &t[0][0];
        int row = bid - 12288;
        const float4* xr = (const float4*)(x + (long)row * Dq);
        float4 v = xr[tid];
        float s  = v.x + v.y + v.z + v.w;
        float ss = v.x * v.x + v.y * v.y + v.z * v.z + v.w * v.w;
        #pragma unroll
        for (int o2 = 16; o2 >= 1; o2 >>= 1) {
            s  += __shfl_xor_sync(0xffffffffu, s,  o2);
            ss += __shfl_xor_sync(0xffffffffu, ss, o2);
        }
        if ((tid & 31) == 0) { red[tid >> 5] = s; red[8 + (tid >> 5)] = ss; }
        __syncthreads();
        float stot = 0.f, sstot = 0.f;
        #pragma unroll
        for (int w = 0; w < 8; w++) { stot += red[w]; sstot += red[8 + w]; }
        float mu  = stot * (1.f / Dq);
        float var = sstot * (1.f / Dq) - mu * mu;
        float inv = rsqrtf(var + LN_EPS);
        float4 gg = ((const float4*)g1)[tid];
        float4 bb = ((const float4*)be1)[tid];
        __half2 p0 = __floats2half2_rn((v.x - mu) * inv * gg.x + bb.x,
                                       (v.y - mu) * inv * gg.y + bb.y);
        __half2 p1 = __floats2half2_rn((v.z - mu) * inv * gg.z + bb.z,
                                       (v.w - mu) * inv * gg.w + bb.w);
        long base = (long)row * Dq + tid * 4;
        *(__half2*)(o_h + base)     = p0;
        *(__half2*)(o_h + base + 2) = p1;
        return;
    }

    int tx = tid & 31, ty = tid >> 5;
    if (bid < 3072) {
        int sh = bid >> 6;
        int tI = bid & 63;
        int s = sh >> 4, h = sh & 15;
        const float* W = (s == 0) ? Wq : (s == 1) ? Wk : Wv;
        const float* in = W + (long)h * Dq * HDq;
        int d0  = (tI >> 1) * 32;
        int hd0 = (tI & 1) * 32;
        #pragma unroll
        for (int i = 0; i < 32; i += 8)
            t[ty + i][tx] = in[(long)(d0 + ty + i) * HDq + hd0 + tx];
        __syncthreads();
        long nrow = (long)s * Dq + h * HDq + hd0;
        #pragma unroll
        for (int i = 0; i < 32; i += 8)
            o_qkv[(nrow + ty + i) * Dq + d0 + tx] = __float2half(t[tx][ty + i]);
        return;
    }

    const float* in; __half* out; int K, N;
    bid -= 3072;
    if (bid < 1024)      { in = Wp; out = o_p; K = Dq;  N = Dq;  }
    else if (bid < 5120) { bid -= 1024; in = W1; out = o_1; K = Dq;  N = DFF; }
    else                 { bid -= 5120; in = W2; out = o_2; K = DFF; N = Dq;  }

    int ntn = N >> 5;
    int k0 = (bid / ntn) * 32;
    int n0 = (bid % ntn) * 32;
    #pragma unroll
    for (int i = 0; i < 32; i += 8)
        t[ty + i][tx] = in[(long)(k0 + ty + i) * N + n0 + tx];
    __syncthreads();
    #pragma unroll
    for (int i = 0; i < 32; i += 8)
        out[(long)(n0 + ty + i) * K + k0 + tx] = __float2half(t[tx][ty + i]);
}

// ---------------------------------------------------------------------------
// Standalone LN (for LN2)
// ---------------------------------------------------------------------------
__global__ void ln_f16(const float* __restrict__ x,
                       const float* __restrict__ g,
                       const float* __restrict__ b,
                       __half* __restrict__ o)
{
    __shared__ float red[16];
    int row = blockIdx.x;
    int t = threadIdx.x;
    const float4* xr = (const float4*)(x + (long)row * Dq);
    float4 v = xr[t];
    float s  = v.x + v.y + v.z + v.w;
    float ss = v.x * v.x + v.y * v.y + v.z * v.z + v.w * v.w;
    #pragma unroll
    for (int o2 = 16; o2 >= 1; o2 >>= 1) {
        s  += __shfl_xor_sync(0xffffffffu, s,  o2);
        ss += __shfl_xor_sync(0xffffffffu, ss, o2);
    }
    if ((t & 31) == 0) { red[t >> 5] = s; red[8 + (t >> 5)] = ss; }
    __syncthreads();
    float stot = 0.f, sstot = 0.f;
    #pragma unroll
    for (int w = 0; w < 8; w++) { stot += red[w]; sstot += red[8 + w]; }
    float mu  = stot * (1.f / Dq);
    float var = sstot * (1.f / Dq) - mu * mu;
    float inv = rsqrtf(var + LN_EPS);
    float4 gg = ((const float4*)g)[t];
    float4 bb = ((const float4*)b)[t];
    __half2 p0 = __floats2half2_rn((v.x - mu) * inv * gg.x + bb.x,
                                   (v.y - mu) * inv * gg.y + bb.y);
    __half2 p1 = __floats2half2_rn((v.z - mu) * inv * gg.z + bb.z,
                                   (v.w - mu) * inv * gg.w + bb.w);
    long base = (long)row * Dq + t * 4;
    *(__half2*)(o + base)     = p0;
    *(__half2*)(o + base + 2) = p1;
}

// ---------------------------------------------------------------------------
// Plain fp16 GEMM (R14 winner): tile 128x128, BK=64, 8 warps (2x4),
// warp tile 64x32, 2-stage cp.async, 2 CTAs/SM, 1 barrier per K-step.
// EPI: 2 +bias+residual fp32; 3 +bias+relu -> fp16; 4 -> fp16 w/ q prescale
// ---------------------------------------------------------------------------
#define KPAD 72
#define AST (128 * KPAD)
#define BST (128 * KPAD)
#define STAGE (AST + BST)           // 18432 halves
#define GEMM_SMEM (2 * STAGE * 2)   // 73728 B -> 2 CTAs/SM verified

template <int EPI>
__global__ void __launch_bounds__(256, 2)
gemm_f16(const __half* __restrict__ A,
         const __half* __restrict__ B,
         const float* __restrict__ bias,
         const float* __restrict__ res,
         float* __restrict__ C,
         __half* __restrict__ Ch,
         int N, int K)
{
    extern __shared__ __half smem[];
    const int tid  = threadIdx.x;
    const int lane = tid & 31;
    const int warp = tid >> 5;
    const int wm = warp >> 2;
    const int wn = warp & 3;
    const int a_r = lane & 15;
    const int a_c = (lane >> 4) << 3;
    const int b_r = (lane & 7) + ((lane >> 4) << 3);
    const int b_c = ((lane >> 3) & 1) << 3;

    const int bm = blockIdx.y, bn = blockIdx.x;
    const __half* A_b = A + (long)bm * 128 * K;
    const __half* B_b = B + (long)bn * 128 * K;

    auto sA = [&](int st) -> __half* { return smem + st * STAGE; };
    auto sB = [&](int st) -> __half* { return smem + st * STAGE + AST; };

    auto ld_stage = [&](int st, int kt) {
        long k0 = (long)kt * 64;
        #pragma unroll
        for (int i = 0; i < 4; i++) {
            int c = tid + i * 256;
            int row = c >> 3, ch = (c & 7) * 8;
            cp16(sA(st) + row * KPAD + ch, A_b + (long)row * K + k0 + ch);
        }
        #pragma unroll
        for (int i = 0; i < 4; i++) {
            int c = tid + i * 256;
            int row = c >> 3, ch = (c & 7) * 8;
            cp16(sB(st) + row * KPAD + ch, B_b + (long)row * K + k0 + ch);
        }
    };

    float acc[4][4][4];
    #pragma unroll
    for (int i = 0; i < 4; i++)
        #pragma unroll
        for (int j = 0; j < 4; j++)
            #pragma unroll
            for (int r = 0; r < 4; r++) acc[i][j][r] = 0.f;

    const int KT = K / 64;
    ld_stage(0, 0); CP_COMMIT();

    for (int kt = 0; kt < KT; kt++) {
        CP_WAIT0();
        __syncthreads();
        if (kt + 1 < KT) {
            ld_stage((kt + 1) & 1, kt + 1);
            CP_COMMIT();
        }
        const __half* pA = sA(kt & 1);
        const __half* pB = sB(kt & 1);

        #pragma unroll
        for (int ks = 0; ks < 4; ks++) {
            const int k16 = ks * 16;
            uint32_t af[4][4], bf[4][2];
            #pragma unroll
            for (int mt = 0; mt < 4; mt++)
                ldmx4(af[mt], pA + (wm * 64 + mt * 16 + a_r) * KPAD + k16 + a_c);
            #pragma unroll
            for (int np = 0; np < 2; np++) {
                int row = wn * 32 + np * 16 + b_r;
                uint32_t r[4];
                ldmx4(r, pB + row * KPAD + k16 + b_c);
                bf[2*np][0] = r[0]; bf[2*np][1] = r[1];
                bf[2*np+1][0] = r[2]; bf[2*np+1][1] = r[3];
            }
            #pragma unroll
            for (int mt = 0; mt < 4; mt++)
                #pragma unroll
                for (int nt = 0; nt < 4; nt++)
                    mma_f16(acc[mt][nt], af[mt], bf[nt]);
        }
    }

    // epilogue
    const int lr4 = lane >> 2;
    const int lc2 = (lane & 3) * 2;
    #pragma unroll
    for (int mt = 0; mt < 4; mt++) {
        #pragma unroll
        for (int nt = 0; nt < 4; nt++) {
            int c = bn * 128 + wn * 32 + nt * 8 + lc2;
            #pragma unroll
            for (int half = 0; half < 2; half++) {
                int r = bm * 128 + wm * 64 + mt * 16 + lr4 + half * 8;
                float v0 = acc[mt][nt][half * 2 + 0];
                float v1 = acc[mt][nt][half * 2 + 1];
                long off = (long)r * N + c;
                if (EPI == 2) {
                    float2 bv = *(const float2*)(bias + c);
                    float2 rv = *(const float2*)(res + off);
                    *(float2*)(C + off) = make_float2(v0 + bv.x + rv.x,
                                                      v1 + bv.y + rv.y);
                } else if (EPI == 3) {
                    float2 bv = *(const float2*)(bias + c);
                    v0 = fmaxf(v0 + bv.x, 0.f);
                    v1 = fmaxf(v1 + bv.y, 0.f);
                    *(__half2*)(Ch + off) = __floats2half2_rn(v0, v1);
                } else {  // EPI == 4: fp16, q cols prescaled
                    float scale = (c < Dq) ? ATT_SCALE : 1.f;
                    *(__half2*)(Ch + off) = __floats2half2_rn(v0 * scale, v1 * scale);
                }
            }
        }
    }
}

// ---------------------------------------------------------------------------
// Flash attention, plain fp16, KV tile 64, double buffered, 2 CTAs/SM.
// ---------------------------------------------------------------------------
#define FPAD 72
#define FLASH_SMEM ((128 * FPAD + 2 * 2 * 64 * FPAD) * 2)   // 55296 B

__global__ void __launch_bounds__(256, 2)
flash_tc(const __half* __restrict__ qkv,
         __half* __restrict__ outp)
{
    extern __shared__ __half sm[];
    __half* QH = sm;

    const int qi  = gridDim.x - 1 - blockIdx.x;
    const int bh  = blockIdx.y;
    const int b   = bh >> 4;
    const int h   = bh & 15;
    const int tid  = threadIdx.x;
    const int lane = tid & 31;
    const int warp = tid >> 5;
    const int g  = lane >> 2;
    const int t2 = (lane & 3) * 2;
    const int a_r = lane & 15;
    const int a_c = (lane >> 4) << 3;
    const int b_r = (lane & 7) + ((lane >> 4) << 3);
    const int b_c = ((lane >> 3) & 1) << 3;

    const long rb = (long)b * Tq;
    const __half* qp = qkv + (rb + qi * 128) * (3 * Dq) + h * HDq;
    const __half* kp = qkv + rb * (3 * Dq) + Dq + h * HDq;
    const __half* vp = qkv + rb * (3 * Dq) + 2 * Dq + h * HDq;

    auto kvbase = [&](int st) -> __half* {
        return sm + 128 * FPAD + st * (2 * 64 * FPAD);
    };
    auto ldkv = [&](int st, int jt) {
        __half* KB = kvbase(st);
        #pragma unroll
        for (int i = 0; i < 2; i++) {
            int c = tid + i * 256;
            int row = c >> 3;
            int c8 = (c & 7) * 8;
            long go = (long)(jt * 64 + row) * (3 * Dq) + c8;
            int so = row * FPAD + c8;
            cp16(KB + so,             kp + go);
            cp16(KB + 64 * FPAD + so, vp + go);
        }
    };

    #pragma unroll
    for (int i = 0; i < 4; i++) {
        int c = tid + i * 256;
        int row = c >> 3;
        int c8 = (c & 7) * 8;
        cp16(QH + row * FPAD + c8, qp + (long)row * (3 * Dq) + c8);
    }
    ldkv(0, 0);
    CP_COMMIT();

    float oacc[8][4];
    #pragma unroll
    for (int nt = 0; nt < 8; nt++)
        #pragma unroll
        for (int e = 0; e < 4; e++) oacc[nt][e] = 0.f;
    float m0 = -1e30f, m1 = -1e30f, l0 = 0.f, l1 = 0.f;

    uint32_t qf[4][4];
    const int qrow0 = qi * 128 + warp * 16 + g;
    const int jmax = 2 * qi + 1;

    for (int jt = 0; jt <= jmax; jt++) {
        CP_WAIT0();
        __syncthreads();
        if (jt < jmax) { ldkv((jt + 1) & 1, jt + 1); CP_COMMIT(); }

        if (jt == 0) {
            #pragma unroll
            for (int kt = 0; kt < 4; kt++)
                ldmx4(qf[kt], QH + (warp * 16 + a_r) * FPAD + kt * 16 + a_c);
        }

        if (jt * 64 <= qi * 128 + warp * 16 + 15) {
            __half* KB = kvbase(jt & 1);
            const __half* KHs = KB;
            const __half* VHs = KB + 64 * FPAD;

            float sacc[8][4];
            #pragma unroll
            for (int nt = 0; nt < 8; nt++)
                #pragma unroll
                for (int e = 0; e < 4; e++) sacc[nt][e] = 0.f;

            #pragma unroll
            for (int kt = 0; kt < 4; kt++) {
                uint32_t bf[8][2];
                #pragma unroll
                for (int np = 0; np < 4; np++) {
                    int row = np * 16 + b_r;
                    uint32_t r[4];
                    ldmx4(r, KHs + row * FPAD + kt * 16 + b_c);
                    bf[2*np][0] = r[0]; bf[2*np][1] = r[1];
                    bf[2*np+1][0] = r[2]; bf[2*np+1][1] = r[3];
                }
                #pragma unroll
                for (int nt = 0; nt < 8; nt++)
                    mma_f16(sacc[nt], qf[kt], bf[nt]);
            }

            if (jt * 64 + 63 > qrow0) {
                #pragma unroll
                for (int nt = 0; nt < 8; nt++) {
                    int key0 = jt * 64 + nt * 8 + t2;
                    if (key0     > qrow0)     sacc[nt][0] = -1e30f;
                    if (key0 + 1 > qrow0)     sacc[nt][1] = -1e30f;
                    if (key0     > qrow0 + 8) sacc[nt][2] = -1e30f;
                    if (key0 + 1 > qrow0 + 8) sacc[nt][3] = -1e30f;
                }
            }

            float mx0 = -1e30f, mx1 = -1e30f;
            #pragma unroll
            for (int nt = 0; nt < 8; nt++) {
                mx0 = fmaxf(mx0, fmaxf(sacc[nt][0], sacc[nt][1]));
                mx1 = fmaxf(mx1, fmaxf(sacc[nt][2], sacc[nt][3]));
            }
            mx0 = fmaxf(mx0, __shfl_xor_sync(0xffffffffu, mx0, 1));
            mx0 = fmaxf(mx0, __shfl_xor_sync(0xffffffffu, mx0, 2));
            mx1 = fmaxf(mx1, __shfl_xor_sync(0xffffffffu, mx1, 1));
            mx1 = fmaxf(mx1, __shfl_xor_sync(0xffffffffu, mx1, 2));
            float mn0 = fmaxf(m0, mx0), mn1 = fmaxf(m1, mx1);
            float a0 = __expf(m0 - mn0), a1 = __expf(m1 - mn1);
            m0 = mn0; m1 = mn1;
            float rs0 = 0.f, rs1 = 0.f;
            #pragma unroll
            for (int nt = 0; nt < 8; nt++) {
                sacc[nt][0] = __expf(sacc[nt][0] - mn0); rs0 += sacc[nt][0];
                sacc[nt][1] = __expf(sacc[nt][1] - mn0); rs0 += sacc[nt][1];
                sacc[nt][2] = __expf(sacc[nt][2] - mn1); rs1 += sacc[nt][2];
                sacc[nt][3] = __expf(sacc[nt][3] - mn1); rs1 += sacc[nt][3];
            }
            rs0 += __shfl_xor_sync(0xffffffffu, rs0, 1);
            rs0 += __shfl_xor_sync(0xffffffffu, rs0, 2);
            rs1 += __shfl_xor_sync(0xffffffffu, rs1, 1);
            rs1 += __shfl_xor_sync(0xffffffffu, rs1, 2);
            l0 = l0 * a0 + rs0;
            l1 = l1 * a1 + rs1;
            #pragma unroll
            for (int nt = 0; nt < 8; nt++) {
                oacc[nt][0] *= a0; oacc[nt][1] *= a0;
                oacc[nt][2] *= a1; oacc[nt][3] *= a1;
            }

            #pragma unroll
            for (int j = 0; j < 4; j++) {
                uint32_t ph[4];
                ph[0] = packh2(sacc[2*j][0],   sacc[2*j][1]);
                ph[1] = packh2(sacc[2*j][2],   sacc[2*j][3]);
                ph[2] = packh2(sacc[2*j+1][0], sacc[2*j+1][1]);
                ph[3] = packh2(sacc[2*j+1][2], sacc[2*j+1][3]);
                #pragma unroll
                for (int nt = 0; nt < 8; nt++) {
                    uint32_t vf[2];
                    ldmx2t(vf[0], vf[1], VHs + (j * 16 + (lane & 15)) * FPAD + nt * 8);
                    mma_f16(oacc[nt], ph, vf);
                }
            }
        }
    }

    float inv0 = 1.f / l0, inv1 = 1.f / l1;
    long row0 = (long)b * Tq + qi * 128 + warp * 16 + g;
    #pragma unroll
    for (int nt = 0; nt < 8; nt++) {
        int col = h * HDq + nt * 8 + t2;
        *(__half2*)(outp + row0 * Dq + col) =
            __floats2half2_rn(oacc[nt][0] * inv0, oacc[nt][1] * inv0);
        *(__half2*)(outp + (row0 + 8) * Dq + col) =
            __floats2half2_rn(oacc[nt][2] * inv1, oacc[nt][3] * inv1);
    }
}

// ---------------------------------------------------------------------------
// Launch
// ---------------------------------------------------------------------------
extern "C" void kernel_launch(void* const* d_in, const int* in_sizes, int n_in,
                              void* d_out, int out_size)
{
    const float* x   = (const float*)d_in[0];
    const float* Wq  = (const float*)d_in[1];
    const float* Wk  = (const float*)d_in[2];
    const float* Wv  = (const float*)d_in[3];
    const float* Wp  = (const float*)d_in[4];
    const float* bp  = (const float*)d_in[5];
    const float* W1  = (const float*)d_in[6];
    const float* b1  = (const float*)d_in[7];
    const float* W2  = (const float*)d_in[8];
    const float* b2  = (const float*)d_in[9];
    const float* g1  = (const float*)d_in[10];
    const float* be1 = (const float*)d_in[11];
    const float* g2  = (const float*)d_in[12];
    const float* be2 = (const float*)d_in[13];
    float* out = (float*)d_out;

    __half *p_h, *p_wqkv, *p_wp, *p_w1, *p_w2, *p_attn, *p_ff, *p_qkv;
    float *p_x1;
    cudaGetSymbolAddress((void**)&p_h,    g_h);
    cudaGetSymbolAddress((void**)&p_wqkv, g_wqkv);
    cudaGetSymbolAddress((void**)&p_wp,   g_wp);
    cudaGetSymbolAddress((void**)&p_w1,   g_w1);
    cudaGetSymbolAddress((void**)&p_w2,   g_w2);
    cudaGetSymbolAddress((void**)&p_qkv,  g_qkv);
    cudaGetSymbolAddress((void**)&p_attn, g_attn);
    cudaGetSymbolAddress((void**)&p_x1,   g_x1);
    cudaGetSymbolAddress((void**)&p_ff,   g_ff);

    cudaFuncSetAttribute(gemm_f16<2>, cudaFuncAttributeMaxDynamicSharedMemorySize, GEMM_SMEM);
    cudaFuncSetAttribute(gemm_f16<3>, cudaFuncAttributeMaxDynamicSharedMemorySize, GEMM_SMEM);
    cudaFuncSetAttribute(gemm_f16<4>, cudaFuncAttributeMaxDynamicSharedMemorySize, GEMM_SMEM);
    cudaFuncSetAttribute(flash_tc,    cudaFuncAttributeMaxDynamicSharedMemorySize, FLASH_SMEM);

    // merged weight prep + LN1 (single launch)
    prep_ln<<<12288 + Mq, 256>>>(Wq, Wk, Wv, Wp, W1, W2, x, g1, be1,
                                 p_wqkv, p_wp, p_w1, p_w2, p_h);

    // QKV projection -> fp16, q prescaled
    gemm_f16<4><<<dim3(3 * Dq / 128, Mq / 128), 256, GEMM_SMEM>>>(
        p_h, p_wqkv, nullptr, nullptr, nullptr, p_qkv, 3 * Dq, Dq);
    // flash attention -> fp16
    flash_tc<<<dim3(Tq / 128, Bq * Hq), 256, FLASH_SMEM>>>(p_qkv, p_attn);
    // output projection + bias + residual(x)
    gemm_f16<2><<<dim3(Dq / 128, Mq / 128), 256, GEMM_SMEM>>>(
        p_attn, p_wp, bp, x, p_x1, nullptr, Dq, Dq);
    // LN2 -> fp16
    ln_f16<<<Mq, 256>>>(p_x1, g2, be2, p_h);
    // FFN up + bias + relu -> fp16
    gemm_f16<3><<<dim3(DFF / 128, Mq / 128), 256, GEMM_SMEM>>>(
        p_h, p_w1, b1, nullptr, nullptr, p_ff, DFF, Dq);
    // FFN down + bias + residual(x1) -> d_out
    gemm_f16<2><<<dim3(Dq / 128, Mq / 128), 256, GEMM_SMEM>>>(
        p_ff, p_w2, b2, p_x1, out, nullptr, Dq, DFF);
}

// round 17
// speedup vs baseline: 1.6943x; 1.0929x over previous
#include <cuda_runtime.h>
#include <cuda_fp16.h>
#include <stdint.h>

// Problem constants
#define Bq   4
#define Tq   2048
#define Dq   1024
#define Hq   16
#define HDq  64
#define Mq   (Bq * Tq)        // 8192
#define DFF  (4 * Dq)         // 4096
#define LN_EPS 1e-5f
#define ATT_SCALE 0.125f

// ---------------------------------------------------------------------------
// Scratch
// ---------------------------------------------------------------------------
__device__ __half g_h[Mq * Dq];            // LN out fp16
__device__ __half g_wqkv[3*Dq*Dq];         // [3D][D] fp16
__device__ __half g_wp[Dq*Dq];             // [D][D] transposed fp16
__device__ __half g_w1[DFF*Dq];            // [4D][D] fp16
__device__ __half g_w2[Dq*DFF];            // [D][4D] fp16
__device__ __half g_qkv[Mq * 3 * Dq];      // q pre-scaled, fp16
__device__ __half g_attn[Mq * Dq];         // flash out fp16
__device__ float  g_x1[Mq * Dq];
__device__ __half g_ff[Mq * DFF];          // FFN hidden fp16

// ---------------------------------------------------------------------------
// Helpers
// ---------------------------------------------------------------------------
__device__ __forceinline__ uint32_t packh2(float x, float y) {
    __half2 h = __floats2half2_rn(x, y);
    return *reinterpret_cast<uint32_t*>(&h);
}

__device__ __forceinline__ void mma_f16(float* c, const uint32_t* a, const uint32_t* b) {
    asm volatile(
        "mma.sync.aligned.m16n8k16.row.col.f32.f16.f16.f32 "
        "{%0,%1,%2,%3}, {%4,%5,%6,%7}, {%8,%9}, {%0,%1,%2,%3};"
        : "+f"(c[0]), "+f"(c[1]), "+f"(c[2]), "+f"(c[3])
        : "r"(a[0]), "r"(a[1]), "r"(a[2]), "r"(a[3]), "r"(b[0]), "r"(b[1]));
}

__device__ __forceinline__ void ldmx4(uint32_t* r, const void* p) {
    uint32_t a = (uint32_t)__cvta_generic_to_shared(p);
    asm volatile("ldmatrix.sync.aligned.m8n8.x4.shared.b16 {%0,%1,%2,%3}, [%4];"
                 : "=r"(r[0]), "=r"(r[1]), "=r"(r[2]), "=r"(r[3]) : "r"(a));
}

__device__ __forceinline__ void ldmx2t(uint32_t& r0, uint32_t& r1, const void* p) {
    uint32_t a = (uint32_t)__cvta_generic_to_shared(p);
    asm volatile("ldmatrix.sync.aligned.m8n8.x2.trans.shared.b16 {%0,%1}, [%2];"
                 : "=r"(r0), "=r"(r1) : "r"(a));
}

__device__ __forceinline__ void cp16(void* sdst, const void* gsrc) {
    unsigned sa = (unsigned)__cvta_generic_to_shared(sdst);
    asm volatile("cp.async.cg.shared.global [%0], [%1], 16;" :: "r"(sa), "l"(gsrc));
}
#define CP_COMMIT() asm volatile("cp.async.commit_group;")
#define CP_WAIT0()  asm volatile("cp.async.wait_group 0;")
#define CP_WAIT1()  asm volatile("cp.async.wait_group 1;")

// Swizzled offset within a 64-half (128 B) row: chunk' = chunk ^ (row & 7).
// off_h = logical column offset in halves (multiple of 8).
__device__ __forceinline__ int swz(int row, int off_h) {
    return row * 64 + (((off_h >> 3) ^ (row & 7)) << 3);
}

// ---------------------------------------------------------------------------
// Merged prep + LN1: blocks [0,12288) transpose weights; [12288,20480) do LN1.
// ---------------------------------------------------------------------------
__global__ void prep_ln(const float* __restrict__ Wq,
                        const float* __restrict__ Wk,
                        const float* __restrict__ Wv,
                        const float* __restrict__ Wp,
                        const float* __restrict__ W1,
                        const float* __restrict__ W2,
                        const float* __restrict__ x,
                        const float* __restrict__ g1,
                        const float* __restrict__ be1,
                        __half* __restrict__ o_qkv,
                        __half* __restrict__ o_p,
                        __half* __restrict__ o_1,
                        __half* __restrict__ o_2,
                        __half* __restrict__ o_h)
{
    __shared__ float t[32][33];
    int bid = blockIdx.x;
    int tid = threadIdx.x;

    if (bid >= 12288) {
        float* red = &t[0][0];
        int row = bid - 12288;
        const float4* xr = (const float4*)(x + (long)row * Dq);
        float4 v = xr[tid];
        float s  = v.x + v.y + v.z + v.w;
        float ss = v.x * v.x + v.y * v.y + v.z * v.z + v.w * v.w;
        #pragma unroll
        for (int o2 = 16; o2 >= 1; o2 >>= 1) {
            s  += __shfl_xor_sync(0xffffffffu, s,  o2);
            ss += __shfl_xor_sync(0xffffffffu, ss, o2);
        }
        if ((tid & 31) == 0) { red[tid >> 5] = s; red[8 + (tid >> 5)] = ss; }
        __syncthreads();
        float stot = 0.f, sstot = 0.f;
        #pragma unroll
        for (int w = 0; w < 8; w++) { stot += red[w]; sstot += red[8 + w]; }
        float mu  = stot * (1.f / Dq);
        float var = sstot * (1.f / Dq) - mu * mu;
        float inv = rsqrtf(var + LN_EPS);
        float4 gg = ((const float4*)g1)[tid];
        float4 bb = ((const float4*)be1)[tid];
        __half2 p0 = __floats2half2_rn((v.x - mu) * inv * gg.x + bb.x,
                                       (v.y - mu) * inv * gg.y + bb.y);
        __half2 p1 = __floats2half2_rn((v.z - mu) * inv * gg.z + bb.z,
                                       (v.w - mu) * inv * gg.w + bb.w);
        long base = (long)row * Dq + tid * 4;
        *(__half2*)(o_h + base)     = p0;
        *(__half2*)(o_h + base + 2) = p1;
        return;
    }

    int tx = tid & 31, ty = tid >> 5;
    if (bid < 3072) {
        int sh = bid >> 6;
        int tI = bid & 63;
        int s = sh >> 4, h = sh & 15;
        const float* W = (s == 0) ? Wq : (s == 1) ? Wk : Wv;
        const float* in = W + (long)h * Dq * HDq;
        int d0  = (tI >> 1) * 32;
        int hd0 = (tI & 1) * 32;
        #pragma unroll
        for (int i = 0; i < 32; i += 8)
            t[ty + i][tx] = in[(long)(d0 + ty + i) * HDq + hd0 + tx];
        __syncthreads();
        long nrow = (long)s * Dq + h * HDq + hd0;
        #pragma unroll
        for (int i = 0; i < 32; i += 8)
            o_qkv[(nrow + ty + i) * Dq + d0 + tx] = __float2half(t[tx][ty + i]);
        return;
    }

    const float* in; __half* out; int K, N;
    bid -= 3072;
    if (bid < 1024)      { in = Wp; out = o_p; K = Dq;  N = Dq;  }
    else if (bid < 5120) { bid -= 1024; in = W1; out = o_1; K = Dq;  N = DFF; }
    else                 { bid -= 5120; in = W2; out = o_2; K = DFF; N = Dq;  }

    int ntn = N >> 5;
    int k0 = (bid / ntn) * 32;
    int n0 = (bid % ntn) * 32;
    #pragma unroll
    for (int i = 0; i < 32; i += 8)
        t[ty + i][tx] = in[(long)(k0 + ty + i) * N + n0 + tx];
    __syncthreads();
    #pragma unroll
    for (int i = 0; i < 32; i += 8)
        out[(long)(n0 + ty + i) * K + k0 + tx] = __float2half(t[tx][ty + i]);
}

// ---------------------------------------------------------------------------
// Standalone LN (for LN2)
// ---------------------------------------------------------------------------
__global__ void ln_f16(const float* __restrict__ x,
                       const float* __restrict__ g,
                       const float* __restrict__ b,
                       __half* __restrict__ o)
{
    __shared__ float red[16];
    int row = blockIdx.x;
    int t = threadIdx.x;
    const float4* xr = (const float4*)(x + (long)row * Dq);
    float4 v = xr[t];
    float s  = v.x + v.y + v.z + v.w;
    float ss = v.x * v.x + v.y * v.y + v.z * v.z + v.w * v.w;
    #pragma unroll
    for (int o2 = 16; o2 >= 1; o2 >>= 1) {
        s  += __shfl_xor_sync(0xffffffffu, s,  o2);
        ss += __shfl_xor_sync(0xffffffffu, ss, o2);
    }
    if ((t & 31) == 0) { red[t >> 5] = s; red[8 + (t >> 5)] = ss; }
    __syncthreads();
    float stot = 0.f, sstot = 0.f;
    #pragma unroll
    for (int w = 0; w < 8; w++) { stot += red[w]; sstot += red[8 + w]; }
    float mu  = stot * (1.f / Dq);
    float var = sstot * (1.f / Dq) - mu * mu;
    float inv = rsqrtf(var + LN_EPS);
    float4 gg = ((const float4*)g)[t];
    float4 bb = ((const float4*)b)[t];
    __half2 p0 = __floats2half2_rn((v.x - mu) * inv * gg.x + bb.x,
                                   (v.y - mu) * inv * gg.y + bb.y);
    __half2 p1 = __floats2half2_rn((v.z - mu) * inv * gg.z + bb.z,
                                   (v.w - mu) * inv * gg.w + bb.w);
    long base = (long)row * Dq + t * 4;
    *(__half2*)(o + base)     = p0;
    *(__half2*)(o + base + 2) = p1;
}

// ---------------------------------------------------------------------------
// Plain fp16 GEMM: tile 128x128, BK=64, XOR-swizzled smem (no pad),
// 3-stage cp.async (prefetch distance 2, wait_group 1), 2 CTAs/SM.
// 8 warps (2x4), warp tile 64x32.
// EPI: 2 +bias+residual fp32; 3 +bias+relu -> fp16; 4 -> fp16 w/ q prescale
// ---------------------------------------------------------------------------
#define AST (128 * 64)
#define BST (128 * 64)
#define STAGE (AST + BST)           // 16384 halves = 32768 B
#define GEMM_SMEM (3 * STAGE * 2)   // 98304 B -> 2 CTAs/SM

template <int EPI>
__global__ void __launch_bounds__(256, 2)
gemm_f16(const __half* __restrict__ A,
         const __half* __restrict__ B,
         const float* __restrict__ bias,
         const float* __restrict__ res,
         float* __restrict__ C,
         __half* __restrict__ Ch,
         int N, int K)
{
    extern __shared__ __half smem[];
    const int tid  = threadIdx.x;
    const int lane = tid & 31;
    const int warp = tid >> 5;
    const int wm = warp >> 2;
    const int wn = warp & 3;
    const int a_r = lane & 15;
    const int a_c = (lane >> 4) << 3;
    const int b_r = (lane & 7) + ((lane >> 4) << 3);
    const int b_c = ((lane >> 3) & 1) << 3;

    const int bm = blockIdx.y, bn = blockIdx.x;
    const __half* A_b = A + (long)bm * 128 * K;
    const __half* B_b = B + (long)bn * 128 * K;

    auto sA = [&](int st) -> __half* { return smem + st * STAGE; };
    auto sB = [&](int st) -> __half* { return smem + st * STAGE + AST; };

    auto ld_stage = [&](int st, int kt) {
        long k0 = (long)kt * 64;
        #pragma unroll
        for (int i = 0; i < 4; i++) {
            int c = tid + i * 256;
            int row = c >> 3, ch = (c & 7) * 8;
            cp16(sA(st) + swz(row, ch), A_b + (long)row * K + k0 + ch);
        }
        #pragma unroll
        for (int i = 0; i < 4; i++) {
            int c = tid + i * 256;
            int row = c >> 3, ch = (c & 7) * 8;
            cp16(sB(st) + swz(row, ch), B_b + (long)row * K + k0 + ch);
        }
    };

    float acc[4][4][4];
    #pragma unroll
    for (int i = 0; i < 4; i++)
        #pragma unroll
        for (int j = 0; j < 4; j++)
            #pragma unroll
            for (int r = 0; r < 4; r++) acc[i][j][r] = 0.f;

    const int KT = K / 64;
    ld_stage(0, 0); CP_COMMIT();
    ld_stage(1, 1); CP_COMMIT();

    int st = 0;
    for (int kt = 0; kt < KT; kt++) {
        if (kt + 1 < KT) { CP_WAIT1(); } else { CP_WAIT0(); }
        __syncthreads();
        if (kt + 2 < KT) {
            int wst = st + 2; if (wst >= 3) wst -= 3;
            ld_stage(wst, kt + 2);
            CP_COMMIT();
        }
        const __half* pA = sA(st);
        const __half* pB = sB(st);

        #pragma unroll
        for (int ks = 0; ks < 4; ks++) {
            const int k16 = ks * 16;
            uint32_t af[4][4], bf[4][2];
            #pragma unroll
            for (int mt = 0; mt < 4; mt++) {
                int row = wm * 64 + mt * 16 + a_r;
                ldmx4(af[mt], pA + swz(row, k16 + a_c));
            }
            #pragma unroll
            for (int np = 0; np < 2; np++) {
                int row = wn * 32 + np * 16 + b_r;
                uint32_t r[4];
                ldmx4(r, pB + swz(row, k16 + b_c));
                bf[2*np][0] = r[0]; bf[2*np][1] = r[1];
                bf[2*np+1][0] = r[2]; bf[2*np+1][1] = r[3];
            }
            #pragma unroll
            for (int mt = 0; mt < 4; mt++)
                #pragma unroll
                for (int nt = 0; nt < 4; nt++)
                    mma_f16(acc[mt][nt], af[mt], bf[nt]);
        }
        if (++st == 3) st = 0;
    }

    // epilogue
    const int lr4 = lane >> 2;
    const int lc2 = (lane & 3) * 2;
    #pragma unroll
    for (int mt = 0; mt < 4; mt++) {
        #pragma unroll
        for (int nt = 0; nt < 4; nt++) {
            int c = bn * 128 + wn * 32 + nt * 8 + lc2;
            #pragma unroll
            for (int half = 0; half < 2; half++) {
                int r = bm * 128 + wm * 64 + mt * 16 + lr4 + half * 8;
                float v0 = acc[mt][nt][half * 2 + 0];
                float v1 = acc[mt][nt][half * 2 + 1];
                long off = (long)r * N + c;
                if (EPI == 2) {
                    float2 bv = *(const float2*)(bias + c);
                    float2 rv = *(const float2*)(res + off);
                    *(float2*)(C + off) = make_float2(v0 + bv.x + rv.x,
                                                      v1 + bv.y + rv.y);
                } else if (EPI == 3) {
                    float2 bv = *(const float2*)(bias + c);
                    v0 = fmaxf(v0 + bv.x, 0.f);
                    v1 = fmaxf(v1 + bv.y, 0.f);
                    *(__half2*)(Ch + off) = __floats2half2_rn(v0, v1);
                } else {  // EPI == 4: fp16, q cols prescaled
                    float scale = (c < Dq) ? ATT_SCALE : 1.f;
                    *(__half2*)(Ch + off) = __floats2half2_rn(v0 * scale, v1 * scale);
                }
            }
        }
    }
}

// ---------------------------------------------------------------------------
// Flash attention, plain fp16, KV tile 64, double buffered, 2 CTAs/SM.
// (unchanged from R16 winner)
// ---------------------------------------------------------------------------
#define FPAD 72
#define FLASH_SMEM ((128 * FPAD + 2 * 2 * 64 * FPAD) * 2)   // 55296 B

__global__ void __launch_bounds__(256, 2)
flash_tc(const __half* __restrict__ qkv,
         __half* __restrict__ outp)
{
    extern __shared__ __half sm[];
    __half* QH = sm;

    const int qi  = gridDim.x - 1 - blockIdx.x;
    const int bh  = blockIdx.y;
    const int b   = bh >> 4;
    const int h   = bh & 15;
    const int tid  = threadIdx.x;
    const int lane = tid & 31;
    const int warp = tid >> 5;
    const int g  = lane >> 2;
    const int t2 = (lane & 3) * 2;
    const int a_r = lane & 15;
    const int a_c = (lane >> 4) << 3;
    const int b_r = (lane & 7) + ((lane >> 4) << 3);
    const int b_c = ((lane >> 3) & 1) << 3;

    const long rb = (long)b * Tq;
    const __half* qp = qkv + (rb + qi * 128) * (3 * Dq) + h * HDq;
    const __half* kp = qkv + rb * (3 * Dq) + Dq + h * HDq;
    const __half* vp = qkv + rb * (3 * Dq) + 2 * Dq + h * HDq;

    auto kvbase = [&](int st) -> __half* {
        return sm + 128 * FPAD + st * (2 * 64 * FPAD);
    };
    auto ldkv = [&](int st, int jt) {
        __half* KB = kvbase(st);
        #pragma unroll
        for (int i = 0; i < 2; i++) {
            int c = tid + i * 256;
            int row = c >> 3;
            int c8 = (c & 7) * 8;
            long go = (long)(jt * 64 + row) * (3 * Dq) + c8;
            int so = row * FPAD + c8;
            cp16(KB + so,             kp + go);
            cp16(KB + 64 * FPAD + so, vp + go);
        }
    };

    #pragma unroll
    for (int i = 0; i < 4; i++) {
        int c = tid + i * 256;
        int row = c >> 3;
        int c8 = (c & 7) * 8;
        cp16(QH + row * FPAD + c8, qp + (long)row * (3 * Dq) + c8);
    }
    ldkv(0, 0);
    CP_COMMIT();

    float oacc[8][4];
    #pragma unroll
    for (int nt = 0; nt < 8; nt++)
        #pragma unroll
        for (int e = 0; e < 4; e++) oacc[nt][e] = 0.f;
    float m0 = -1e30f, m1 = -1e30f, l0 = 0.f, l1 = 0.f;

    uint32_t qf[4][4];
    const int qrow0 = qi * 128 + warp * 16 + g;
    const int jmax = 2 * qi + 1;

    for (int jt = 0; jt <= jmax; jt++) {
        CP_WAIT0();
        __syncthreads();
        if (jt < jmax) { ldkv((jt + 1) & 1, jt + 1); CP_COMMIT(); }

        if (jt == 0) {
            #pragma unroll
            for (int kt = 0; kt < 4; kt++)
                ldmx4(qf[kt], QH + (warp * 16 + a_r) * FPAD + kt * 16 + a_c);
        }

        if (jt * 64 <= qi * 128 + warp * 16 + 15) {
            __half* KB = kvbase(jt & 1);
            const __half* KHs = KB;
            const __half* VHs = KB + 64 * FPAD;

            float sacc[8][4];
            #pragma unroll
            for (int nt = 0; nt < 8; nt++)
                #pragma unroll
                for (int e = 0; e < 4; e++) sacc[nt][e] = 0.f;

            #pragma unroll
            for (int kt = 0; kt < 4; kt++) {
                uint32_t bf[8][2];
                #pragma unroll
                for (int np = 0; np < 4; np++) {
                    int row = np * 16 + b_r;
                    uint32_t r[4];
                    ldmx4(r, KHs + row * FPAD + kt * 16 + b_c);
                    bf[2*np][0] = r[0]; bf[2*np][1] = r[1];
                    bf[2*np+1][0] = r[2]; bf[2*np+1][1] = r[3];
                }
                #pragma unroll
                for (int nt = 0; nt < 8; nt++)
                    mma_f16(sacc[nt], qf[kt], bf[nt]);
            }

            if (jt * 64 + 63 > qrow0) {
                #pragma unroll
                for (int nt = 0; nt < 8; nt++) {
                    int key0 = jt * 64 + nt * 8 + t2;
                    if (key0     > qrow0)     sacc[nt][0] = -1e30f;
                    if (key0 + 1 > qrow0)     sacc[nt][1] = -1e30f;
                    if (key0     > qrow0 + 8) sacc[nt][2] = -1e30f;
                    if (key0 + 1 > qrow0 + 8) sacc[nt][3] = -1e30f;
                }
            }

            float mx0 = -1e30f, mx1 = -1e30f;
            #pragma unroll
            for (int nt = 0; nt < 8; nt++) {
                mx0 = fmaxf(mx0, fmaxf(sacc[nt][0], sacc[nt][1]));
                mx1 = fmaxf(mx1, fmaxf(sacc[nt][2], sacc[nt][3]));
            }
            mx0 = fmaxf(mx0, __shfl_xor_sync(0xffffffffu, mx0, 1));
            mx0 = fmaxf(mx0, __shfl_xor_sync(0xffffffffu, mx0, 2));
            mx1 = fmaxf(mx1, __shfl_xor_sync(0xffffffffu, mx1, 1));
            mx1 = fmaxf(mx1, __shfl_xor_sync(0xffffffffu, mx1, 2));
            float mn0 = fmaxf(m0, mx0), mn1 = fmaxf(m1, mx1);
            float a0 = __expf(m0 - mn0), a1 = __expf(m1 - mn1);
            m0 = mn0; m1 = mn1;
            float rs0 = 0.f, rs1 = 0.f;
            #pragma unroll
            for (int nt = 0; nt < 8; nt++) {
                sacc[nt][0] = __expf(sacc[nt][0] - mn0); rs0 += sacc[nt][0];
                sacc[nt][1] = __expf(sacc[nt][1] - mn0); rs0 += sacc[nt][1];
                sacc[nt][2] = __expf(sacc[nt][2] - mn1); rs1 += sacc[nt][2];
                sacc[nt][3] = __expf(sacc[nt][3] - mn1); rs1 += sacc[nt][3];
            }
            rs0 += __shfl_xor_sync(0xffffffffu, rs0, 1);
            rs0 += __shfl_xor_sync(0xffffffffu, rs0, 2);
            rs1 += __shfl_xor_sync(0xffffffffu, rs1, 1);
            rs1 += __shfl_xor_sync(0xffffffffu, rs1, 2);
            l0 = l0 * a0 + rs0;
            l1 = l1 * a1 + rs1;
            #pragma unroll
            for (int nt = 0; nt < 8; nt++) {
                oacc[nt][0] *= a0; oacc[nt][1] *= a0;
                oacc[nt][2] *= a1; oacc[nt][3] *= a1;
            }

            #pragma unroll
            for (int j = 0; j < 4; j++) {
                uint32_t ph[4];
                ph[0] = packh2(sacc[2*j][0],   sacc[2*j][1]);
                ph[1] = packh2(sacc[2*j][2],   sacc[2*j][3]);
                ph[2] = packh2(sacc[2*j+1][0], sacc[2*j+1][1]);
                ph[3] = packh2(sacc[2*j+1][2], sacc[2*j+1][3]);
                #pragma unroll
                for (int nt = 0; nt < 8; nt++) {
                    uint32_t vf[2];
                    ldmx2t(vf[0], vf[1], VHs + (j * 16 + (lane & 15)) * FPAD + nt * 8);
                    mma_f16(oacc[nt], ph, vf);
                }
            }
        }
    }

    float inv0 = 1.f / l0, inv1 = 1.f / l1;
    long row0 = (long)b * Tq + qi * 128 + warp * 16 + g;
    #pragma unroll
    for (int nt = 0; nt < 8; nt++) {
        int col = h * HDq + nt * 8 + t2;
        *(__half2*)(outp + row0 * Dq + col) =
            __floats2half2_rn(oacc[nt][0] * inv0, oacc[nt][1] * inv0);
        *(__half2*)(outp + (row0 + 8) * Dq + col) =
            __floats2half2_rn(oacc[nt][2] * inv1, oacc[nt][3] * inv1);
    }
}

// ---------------------------------------------------------------------------
// Launch
// ---------------------------------------------------------------------------
extern "C" void kernel_launch(void* const* d_in, const int* in_sizes, int n_in,
                              void* d_out, int out_size)
{
    const float* x   = (const float*)d_in[0];
    const float* Wq  = (const float*)d_in[1];
    const float* Wk  = (const float*)d_in[2];
    const float* Wv  = (const float*)d_in[3];
    const float* Wp  = (const float*)d_in[4];
    const float* bp  = (const float*)d_in[5];
    const float* W1  = (const float*)d_in[6];
    const float* b1  = (const float*)d_in[7];
    const float* W2  = (const float*)d_in[8];
    const float* b2  = (const float*)d_in[9];
    const float* g1  = (const float*)d_in[10];
    const float* be1 = (const float*)d_in[11];
    const float* g2  = (const float*)d_in[12];
    const float* be2 = (const float*)d_in[13];
    float* out = (float*)d_out;

    __half *p_h, *p_wqkv, *p_wp, *p_w1, *p_w2, *p_attn, *p_ff, *p_qkv;
    float *p_x1;
    cudaGetSymbolAddress((void**)&p_h,    g_h);
    cudaGetSymbolAddress((void**)&p_wqkv, g_wqkv);
    cudaGetSymbolAddress((void**)&p_wp,   g_wp);
    cudaGetSymbolAddress((void**)&p_w1,   g_w1);
    cudaGetSymbolAddress((void**)&p_w2,   g_w2);
    cudaGetSymbolAddress((void**)&p_qkv,  g_qkv);
    cudaGetSymbolAddress((void**)&p_attn, g_attn);
    cudaGetSymbolAddress((void**)&p_x1,   g_x1);
    cudaGetSymbolAddress((void**)&p_ff,   g_ff);

    cudaFuncSetAttribute(gemm_f16<2>, cudaFuncAttributeMaxDynamicSharedMemorySize, GEMM_SMEM);
    cudaFuncSetAttribute(gemm_f16<3>, cudaFuncAttributeMaxDynamicSharedMemorySize, GEMM_SMEM);
    cudaFuncSetAttribute(gemm_f16<4>, cudaFuncAttributeMaxDynamicSharedMemorySize, GEMM_SMEM);
    cudaFuncSetAttribute(flash_tc,    cudaFuncAttributeMaxDynamicSharedMemorySize, FLASH_SMEM);

    // merged weight prep + LN1 (single launch)
    prep_ln<<<12288 + Mq, 256>>>(Wq, Wk, Wv, Wp, W1, W2, x, g1, be1,
                                 p_wqkv, p_wp, p_w1, p_w2, p_h);

    // QKV projection -> fp16, q prescaled
    gemm_f16<4><<<dim3(3 * Dq / 128, Mq / 128), 256, GEMM_SMEM>>>(
        p_h, p_wqkv, nullptr, nullptr, nullptr, p_qkv, 3 * Dq, Dq);
    // flash attention -> fp16
    flash_tc<<<dim3(Tq / 128, Bq * Hq), 256, FLASH_SMEM>>>(p_qkv, p_attn);
    // output projection + bias + residual(x)
    gemm_f16<2><<<dim3(Dq / 128, Mq / 128), 256, GEMM_SMEM>>>(
        p_attn, p_wp, bp, x, p_x1, nullptr, Dq, Dq);
    // LN2 -> fp16
    ln_f16<<<Mq, 256>>>(p_x1, g2, be2, p_h);
    // FFN up + bias + relu -> fp16
    gemm_f16<3><<<dim3(DFF / 128, Mq / 128), 256, GEMM_SMEM>>>(
        p_h, p_w1, b1, nullptr, nullptr, p_ff, DFF, Dq);
    // FFN down + bias + residual(x1) -> d_out
    gemm_f16<2><<<dim3(Dq / 128, Mq / 128), 256, GEMM_SMEM>>>(
        p_ff, p_w2, b2, p_x1, out, nullptr, Dq, DFF);
}